// round 1
// baseline (speedup 1.0000x reference)
#include <cuda_runtime.h>
#include <math.h>

// Problem constants
#define T_TOKENS 8192      // B*S = 4*2048
#define D_DIM    1024
#define E_EXP    8
#define I_DIM    938
#define GU_DIM   1876      // 2*I
#define H_STRIDE 1888      // GU_DIM padded to mult of 32 floats (128B)
#define A_STRIDE 944       // I padded to mult of 16 floats

// ---------------- scratch (static device memory; allocation-free) ----------------
__device__ int   g_cnt[E_EXP];
__device__ int   g_tok[E_EXP * T_TOKENS];
__device__ float g_wt [E_EXP * T_TOKENS];
__device__ float g_Hs[(long long)T_TOKENS * H_STRIDE];                 // shared H
__device__ float g_As[(long long)T_TOKENS * A_STRIDE];                 // shared silu(g)*u
__device__ float g_Hr[(long long)E_EXP * T_TOKENS * H_STRIDE];         // routed H slabs
__device__ float g_Ar[(long long)E_EXP * T_TOKENS * A_STRIDE];         // routed act slabs
__device__ float g_dp[(long long)(E_EXP + 1) * D_DIM * A_STRIDE];      // padded down: slot0=shared, 1..8=experts

// ---------------- tiny helpers ----------------
__global__ void zero_cnt_kernel(int* cnt) {
    if (threadIdx.x < E_EXP) cnt[threadIdx.x] = 0;
}

// Repack down matrices [*,1024,938] -> [*,1024,944] zero padded (16B-aligned rows).
__global__ void repack_down_kernel(const float* __restrict__ sdn,
                                   const float* __restrict__ edn,
                                   float* __restrict__ dp) {
    long long idx = (long long)blockIdx.x * blockDim.x + threadIdx.x;
    const long long total = (long long)(E_EXP + 1) * D_DIM * A_STRIDE;
    if (idx >= total) return;
    int i = (int)(idx % A_STRIDE);
    long long r = idx / A_STRIDE;
    int row = (int)(r % D_DIM);
    int s   = (int)(r / D_DIM);
    float v = 0.f;
    if (i < I_DIM) {
        if (s == 0) v = sdn[(long long)row * I_DIM + i];
        else        v = edn[((long long)(s - 1) * D_DIM + row) * I_DIM + i];
    }
    dp[idx] = v;
}

// ---------------- router: logits -> softmax -> top2 -> bucket tokens ----------------
__global__ void router_kernel(const float* __restrict__ x,
                              const float* __restrict__ gw,
                              int* __restrict__ cnt,
                              int* __restrict__ tok,
                              float* __restrict__ wt) {
    __shared__ float sgw[E_EXP * D_DIM];   // 32KB
    const int tid = threadIdx.x;
    for (int i = tid; i < E_EXP * D_DIM; i += blockDim.x) sgw[i] = gw[i];
    __syncthreads();

    const int warp = tid >> 5;
    const int lane = tid & 31;
    const int t = blockIdx.x * 8 + warp;           // grid=1024 -> t < 8192 always
    const float* xt = x + (long long)t * D_DIM;

    float acc[E_EXP];
#pragma unroll
    for (int e = 0; e < E_EXP; e++) acc[e] = 0.f;
    for (int k = lane; k < D_DIM; k += 32) {
        float xv = xt[k];
#pragma unroll
        for (int e = 0; e < E_EXP; e++) acc[e] += xv * sgw[e * D_DIM + k];
    }
#pragma unroll
    for (int e = 0; e < E_EXP; e++) {
#pragma unroll
        for (int off = 16; off; off >>= 1)
            acc[e] += __shfl_xor_sync(0xffffffffu, acc[e], off);
    }
    if (lane == 0) {
        float mx = acc[0];
#pragma unroll
        for (int e = 1; e < E_EXP; e++) mx = fmaxf(mx, acc[e]);
        float p[E_EXP], Z = 0.f;
#pragma unroll
        for (int e = 0; e < E_EXP; e++) { p[e] = expf(acc[e] - mx); Z += p[e]; }
#pragma unroll
        for (int e = 0; e < E_EXP; e++) p[e] /= Z;
        // top2, first occurrence on ties (matches jax.lax.top_k)
        int i1 = 0;
#pragma unroll
        for (int e = 1; e < E_EXP; e++) if (p[e] > p[i1]) i1 = e;
        int i2 = (i1 == 0) ? 1 : 0;
#pragma unroll
        for (int e = 0; e < E_EXP; e++) if (e != i2 && e != i1 && p[e] > p[i2]) i2 = e;
        float denom = p[i1] + p[i2] + 1e-8f;
        float w1 = p[i1] / denom;
        float w2 = p[i2] / denom;
        int pos1 = atomicAdd(&cnt[i1], 1);
        tok[i1 * T_TOKENS + pos1] = t;
        wt [i1 * T_TOKENS + pos1] = w1;
        int pos2 = atomicAdd(&cnt[i2], 1);
        tok[i2 * T_TOKENS + pos2] = t;
        wt [i2 * T_TOKENS + pos2] = w2;
    }
}

// ---------------- swiglu: A[m,i] = silu(H[m,i]) * H[m,i+I], zero-pads i in [938,944) --------
__global__ void swiglu_kernel(const float* __restrict__ H, float* __restrict__ Aout,
                              const int* __restrict__ cntPtr, int Mfix,
                              long long strideHe, long long strideAe) {
    const int e = blockIdx.z;
    const int M = cntPtr ? cntPtr[e] : Mfix;
    const int m = blockIdx.y;
    if (m >= M) return;
    const float* h = H + (long long)e * strideHe + (long long)m * H_STRIDE;
    float* a = Aout + (long long)e * strideAe + (long long)m * A_STRIDE;
    for (int i = threadIdx.x; i < A_STRIDE; i += blockDim.x) {
        float v = 0.f;
        if (i < I_DIM) {
            float g = h[i];
            float u = h[i + I_DIM];
            v = (g / (1.f + expf(-g))) * u;
        }
        a[i] = v;
    }
}

// ---------------- SGEMM 128x128x16, NT layout (C[m,n] = sum_k A[m,k]*B[n,k]) ----------------
// EPI 0: plain store with (m<M, n<N) guards.
// EPI 1: weighted atomic scatter-add into C rows tok[m] with weight wt[m].
template<bool GATHER_A, int EPI>
__launch_bounds__(256, 2)
__global__ void sgemm_kernel(const float* __restrict__ Abase, long long strideAe, int lda,
                             const float* __restrict__ Bbase, long long strideBe, int ldb,
                             float* __restrict__ Cbase, long long strideCe, int ldc,
                             int Mfix, int N, int K,
                             const int* __restrict__ cntPtr,
                             const int* __restrict__ tokBase,
                             const float* __restrict__ wtBase) {
    const int e = blockIdx.z;
    const int M = cntPtr ? cntPtr[e] : Mfix;
    const int m0 = blockIdx.y * 128;
    if (m0 >= M) return;
    const int n0 = blockIdx.x * 128;

    const float* A = Abase + (long long)e * strideAe;
    const float* B = Bbase + (long long)e * strideBe;
    float* C = Cbase + (long long)e * strideCe;
    const int* tok = tokBase ? (tokBase + e * T_TOKENS) : nullptr;
    const float* wts = wtBase ? (wtBase + e * T_TOKENS) : nullptr;

    __shared__ __align__(16) float As[16][128];
    __shared__ __align__(16) float Bs[16][128];

    const int tid  = threadIdx.x;
    const int lrow = tid >> 1;            // 0..127 (row of tile being loaded)
    const int lkq  = (tid & 1) * 2;       // 0 or 2 (which pair of k-quads)

    // resolve A global row (gather for routed GEMM1)
    long long aRow;
    if (GATHER_A) {
        int mg = m0 + lrow;
        aRow = (mg < M) ? tok[mg] : 0;
    } else {
        aRow = m0 + lrow;
    }
    const int bn = n0 + lrow;

    float acc[8][8];
#pragma unroll
    for (int i = 0; i < 8; i++)
#pragma unroll
        for (int j = 0; j < 8; j++) acc[i][j] = 0.f;

    const int m_off = (tid >> 4) * 8;
    const int n_off = (tid & 15) * 8;

    for (int k0 = 0; k0 < K; k0 += 16) {
        // load A tile (transposed into As[k][m])
#pragma unroll
        for (int q = 0; q < 2; q++) {
            int kq = lkq + q;
            float4 v = *(const float4*)(A + aRow * lda + k0 + kq * 4);
            As[kq * 4 + 0][lrow] = v.x;
            As[kq * 4 + 1][lrow] = v.y;
            As[kq * 4 + 2][lrow] = v.z;
            As[kq * 4 + 3][lrow] = v.w;
        }
        // load B tile (transposed into Bs[k][n]), guard n
#pragma unroll
        for (int q = 0; q < 2; q++) {
            int kq = lkq + q;
            float4 v = make_float4(0.f, 0.f, 0.f, 0.f);
            if (bn < N) v = *(const float4*)(B + (long long)bn * ldb + k0 + kq * 4);
            Bs[kq * 4 + 0][lrow] = v.x;
            Bs[kq * 4 + 1][lrow] = v.y;
            Bs[kq * 4 + 2][lrow] = v.z;
            Bs[kq * 4 + 3][lrow] = v.w;
        }
        __syncthreads();
#pragma unroll
        for (int kk = 0; kk < 16; kk++) {
            float4 a0 = *(const float4*)&As[kk][m_off];
            float4 a1 = *(const float4*)&As[kk][m_off + 4];
            float4 b0 = *(const float4*)&Bs[kk][n_off];
            float4 b1 = *(const float4*)&Bs[kk][n_off + 4];
            float av[8] = {a0.x, a0.y, a0.z, a0.w, a1.x, a1.y, a1.z, a1.w};
            float bv[8] = {b0.x, b0.y, b0.z, b0.w, b1.x, b1.y, b1.z, b1.w};
#pragma unroll
            for (int i = 0; i < 8; i++)
#pragma unroll
                for (int j = 0; j < 8; j++)
                    acc[i][j] = fmaf(av[i], bv[j], acc[i][j]);
        }
        __syncthreads();
    }

    // epilogue
    if (EPI == 0) {
#pragma unroll
        for (int i = 0; i < 8; i++) {
            int gm = m0 + m_off + i;
            if (gm >= M) continue;
            float* crow = C + (long long)gm * ldc;
#pragma unroll
            for (int j = 0; j < 8; j++) {
                int gn = n0 + n_off + j;
                if (gn < N) crow[gn] = acc[i][j];
            }
        }
    } else {
#pragma unroll
        for (int i = 0; i < 8; i++) {
            int gm = m0 + m_off + i;
            if (gm >= M) continue;
            int t = tok[gm];
            float w = wts[gm];
            float* crow = C + (long long)t * ldc;
#pragma unroll
            for (int j = 0; j < 8; j++) {
                int gn = n0 + n_off + j;
                if (gn < N) atomicAdd(&crow[gn], w * acc[i][j]);
            }
        }
    }
}

// ---------------- host launch ----------------
extern "C" void kernel_launch(void* const* d_in, const int* in_sizes, int n_in,
                              void* d_out, int out_size) {
    const float* x   = (const float*)d_in[0];   // [4,2048,1024]
    const float* gw  = (const float*)d_in[1];   // [8,1024]
    const float* sgu = (const float*)d_in[2];   // [1876,1024]
    const float* sdn = (const float*)d_in[3];   // [1024,938]
    const float* egu = (const float*)d_in[4];   // [8,1876,1024]
    const float* edn = (const float*)d_in[5];   // [8,1024,938]
    float* out = (float*)d_out;                 // [4,2048,1024]

    void *pCnt, *pTok, *pWt, *pHs, *pAs, *pHr, *pAr, *pDp;
    cudaGetSymbolAddress(&pCnt, g_cnt);
    cudaGetSymbolAddress(&pTok, g_tok);
    cudaGetSymbolAddress(&pWt,  g_wt);
    cudaGetSymbolAddress(&pHs,  g_Hs);
    cudaGetSymbolAddress(&pAs,  g_As);
    cudaGetSymbolAddress(&pHr,  g_Hr);
    cudaGetSymbolAddress(&pAr,  g_Ar);
    cudaGetSymbolAddress(&pDp,  g_dp);
    int*   cnt = (int*)pCnt;
    int*   tok = (int*)pTok;
    float* wts = (float*)pWt;
    float* Hs  = (float*)pHs;
    float* Asc = (float*)pAs;
    float* Hr  = (float*)pHr;
    float* Ar  = (float*)pAr;
    float* dp  = (float*)pDp;

    // 1) reset counters + router
    zero_cnt_kernel<<<1, 32>>>(cnt);
    router_kernel<<<T_TOKENS / 8, 256>>>(x, gw, cnt, tok, wts);

    // 2) repack down matrices into 944-stride padded layout
    {
        long long total = (long long)(E_EXP + 1) * D_DIM * A_STRIDE;
        int blocks = (int)((total + 255) / 256);
        repack_down_kernel<<<blocks, 256>>>(sdn, edn, dp);
    }

    // 3) shared expert: H = X @ Wgu^T   (M=8192, N=1876, K=1024)
    sgemm_kernel<false, 0><<<dim3(15, 64, 1), 256>>>(
        x, 0LL, D_DIM, sgu, 0LL, D_DIM, Hs, 0LL, H_STRIDE,
        T_TOKENS, GU_DIM, D_DIM, nullptr, nullptr, nullptr);

    // 4) shared swiglu
    swiglu_kernel<<<dim3(1, T_TOKENS, 1), 256>>>(Hs, Asc, nullptr, T_TOKENS, 0LL, 0LL);

    // 5) shared expert: out = A @ downP^T  (M=8192, N=1024, K=944; writes ALL of out)
    sgemm_kernel<false, 0><<<dim3(8, 64, 1), 256>>>(
        Asc, 0LL, A_STRIDE, dp /*slot 0*/, 0LL, A_STRIDE, out, 0LL, D_DIM,
        T_TOKENS, D_DIM, A_STRIDE, nullptr, nullptr, nullptr);

    // 6) routed experts GEMM1 (gathered): Hr[e] = X[tok] @ Egup[e]^T
    sgemm_kernel<true, 0><<<dim3(15, 64, E_EXP), 256>>>(
        x, 0LL, D_DIM,
        egu, (long long)GU_DIM * D_DIM, D_DIM,
        Hr, (long long)T_TOKENS * H_STRIDE, H_STRIDE,
        0, GU_DIM, D_DIM, cnt, tok, nullptr);

    // 7) routed swiglu
    swiglu_kernel<<<dim3(1, T_TOKENS, E_EXP), 256>>>(
        Hr, Ar, cnt, 0,
        (long long)T_TOKENS * H_STRIDE, (long long)T_TOKENS * A_STRIDE);

    // 8) routed GEMM2 + weighted scatter-add into out
    sgemm_kernel<false, 1><<<dim3(8, 64, E_EXP), 256>>>(
        Ar, (long long)T_TOKENS * A_STRIDE, A_STRIDE,
        dp + (long long)D_DIM * A_STRIDE /*slots 1..8*/, (long long)D_DIM * A_STRIDE, A_STRIDE,
        out, 0LL, D_DIM,
        0, D_DIM, A_STRIDE, cnt, tok, wts);
}

// round 3
// speedup vs baseline: 2.0391x; 2.0391x over previous
#include <cuda_runtime.h>
#include <cuda_bf16.h>
#include <math.h>
#include <stdint.h>

typedef __nv_bfloat16 bf16;

#define T_TOKENS 8192
#define D_DIM    1024
#define E_EXP    8
#define I_DIM    938
#define GU_DIM   1876
#define GUP      1920      // 2I padded to 15*128
#define IP       960       // I padded to 15*64
#define NSLOT    9         // slot0 = shared, 1..8 = routed

#define BM 128
#define BN 128
#define BK 64
#define SROW 144                    // smem row stride bytes (64 bf16 data + 8 bf16 pad)
#define TILEB (128*SROW)            // 18432 B
#define STAGEB (4*TILEB)            // Ah, Al, Bh, Bl
#define SMEM_DYN (1024 + 2*STAGEB)  // 148480 B

// ---------------- static scratch ----------------
__device__ int    g_cnt[E_EXP];
__device__ int    g_tok[E_EXP * T_TOKENS];
__device__ int4   g_tk2[T_TOKENS];      // (e1,p1,e2,p2)
__device__ float2 g_w2 [T_TOKENS];      // (w1,w2)
__device__ bf16   g_xhi[T_TOKENS * D_DIM];
__device__ bf16   g_xlo[T_TOKENS * D_DIM];
__device__ bf16   g_wgu_hi[NSLOT * GUP * D_DIM];   // interleaved (gate_i, up_i) rows
__device__ bf16   g_wgu_lo[NSLOT * GUP * D_DIM];
__device__ bf16   g_wdn_hi[NSLOT * D_DIM * IP];
__device__ bf16   g_wdn_lo[NSLOT * D_DIM * IP];
__device__ bf16   g_act_hi[(size_t)NSLOT * T_TOKENS * IP];
__device__ bf16   g_act_lo[(size_t)NSLOT * T_TOKENS * IP];
__device__ float  g_ybuf[(size_t)E_EXP * T_TOKENS * D_DIM];

// ---------------- helpers ----------------
__device__ __forceinline__ uint32_t smem_u32(const void* p) {
    uint32_t a;
    asm("{ .reg .u64 t; cvta.to.shared.u64 t, %1; cvt.u32.u64 %0, t; }" : "=r"(a) : "l"(p));
    return a;
}
__device__ __forceinline__ void cp16(uint32_t s, const void* g) {
    asm volatile("cp.async.cg.shared.global [%0], [%1], 16;" :: "r"(s), "l"(g));
}
__device__ __forceinline__ void ldsm4(uint32_t* r, uint32_t a) {
    asm volatile("ldmatrix.sync.aligned.m8n8.x4.shared.b16 {%0,%1,%2,%3}, [%4];"
        : "=r"(r[0]), "=r"(r[1]), "=r"(r[2]), "=r"(r[3]) : "r"(a));
}
__device__ __forceinline__ void mma16816(float* d, const uint32_t* a, const uint32_t* b) {
    asm volatile(
        "mma.sync.aligned.m16n8k16.row.col.f32.bf16.bf16.f32 "
        "{%0,%1,%2,%3}, {%4,%5,%6,%7}, {%8,%9}, {%0,%1,%2,%3};"
        : "+f"(d[0]), "+f"(d[1]), "+f"(d[2]), "+f"(d[3])
        : "r"(a[0]), "r"(a[1]), "r"(a[2]), "r"(a[3]), "r"(b[0]), "r"(b[1]));
}
__device__ __forceinline__ void split2(float v, bf16& h, bf16& l) {
    h = __float2bfloat16(v);
    l = __float2bfloat16(v - __bfloat162float(h));
}

// ---------------- mainloop: 128x128 tile, NT, 3-term bf16 split ----------------
__device__ __forceinline__ void gemm_mainloop(
    uint32_t s0,
    const bf16* sa_h, const bf16* sa_l,   // per-thread A row ptr (row = tid>>1)
    const bf16* sb_h, const bf16* sb_l,   // per-thread B row ptr
    int NC, int tid, float acc[4][4][4])
{
    const int lane = tid & 31, wid = tid >> 5;
    const int mwb = (wid >> 2) * 64;
    const int nwb = (wid & 3) * 32;
    const int lcp0 = (tid & 1) * 4;
    const uint32_t wbase = (uint32_t)(tid >> 1) * SROW + lcp0 * 16;

#define LOAD_STAGE(st, c) do {                                              \
        uint32_t b_ = s0 + (st) * STAGEB + wbase;                           \
        int k0_ = (c) * BK + lcp0 * 8;                                      \
        _Pragma("unroll")                                                   \
        for (int j = 0; j < 4; j++) {                                       \
            cp16(b_ + 0*TILEB + j*16, sa_h + k0_ + j*8);                    \
            cp16(b_ + 1*TILEB + j*16, sa_l + k0_ + j*8);                    \
            cp16(b_ + 2*TILEB + j*16, sb_h + k0_ + j*8);                    \
            cp16(b_ + 3*TILEB + j*16, sb_l + k0_ + j*8);                    \
        }                                                                   \
        asm volatile("cp.async.commit_group;" ::: "memory");                \
    } while (0)

    LOAD_STAGE(0, 0);

    const int arow   = mwb + (lane & 15);
    const int acolB0 = (lane >> 4) * 16;
    const int bn     = nwb + ((lane >> 4) * 8) + (lane & 7);
    const int bkB0   = ((lane >> 3) & 1) * 16;

    for (int c = 0; c < NC; c++) {
        const int st = c & 1;
        if (c + 1 < NC) {
            LOAD_STAGE(st ^ 1, c + 1);
            asm volatile("cp.async.wait_group 1;" ::: "memory");
        } else {
            asm volatile("cp.async.wait_group 0;" ::: "memory");
        }
        __syncthreads();
        const uint32_t tb = s0 + st * STAGEB;
#pragma unroll
        for (int ks = 0; ks < 4; ks++) {
            uint32_t ah[4][4], al[4][4], bh[2][4], bl[2][4];
            const uint32_t acolB = ks * 32 + acolB0;
#pragma unroll
            for (int mi = 0; mi < 4; mi++) {
                uint32_t ra = tb + (uint32_t)(arow + mi * 16) * SROW + acolB;
                ldsm4(ah[mi], ra + 0 * TILEB);
                ldsm4(al[mi], ra + 1 * TILEB);
            }
            const uint32_t bcolB = ks * 32 + bkB0;
#pragma unroll
            for (int ni = 0; ni < 2; ni++) {
                uint32_t rb = tb + (uint32_t)(bn + ni * 16) * SROW + bcolB;
                ldsm4(bh[ni], rb + 2 * TILEB);
                ldsm4(bl[ni], rb + 3 * TILEB);
            }
#pragma unroll
            for (int mi = 0; mi < 4; mi++)
#pragma unroll
                for (int ni = 0; ni < 4; ni++) {
                    const uint32_t* Bh = &bh[ni >> 1][(ni & 1) * 2];
                    const uint32_t* Bl = &bl[ni >> 1][(ni & 1) * 2];
                    mma16816(acc[mi][ni], ah[mi], Bh);
                    mma16816(acc[mi][ni], ah[mi], Bl);
                    mma16816(acc[mi][ni], al[mi], Bh);
                }
        }
        __syncthreads();
    }
#undef LOAD_STAGE
}

// ---------------- GEMM1: H = X @ Wgu^T, fused swiglu -> act hi/lo ----------------
__global__ void __launch_bounds__(256, 1) gemm1_kernel() {
    extern __shared__ char smem[];
    int* rowids = (int*)smem;
    const uint32_t s0 = smem_u32(smem) + 1024;
    const int tid = threadIdx.x;
    const int s = blockIdx.z, m0 = blockIdx.y * BM, n0 = blockIdx.x * BN;
    const int M = (s == 0) ? T_TOKENS : g_cnt[s - 1];
    if (m0 >= M) return;

    if (tid < 128) {
        int am = m0 + tid;
        int r;
        if (s == 0) r = am;
        else        r = g_tok[(s - 1) * T_TOKENS + (am < M ? am : M - 1)];
        rowids[tid] = r;
    }
    __syncthreads();

    const long long arow = rowids[tid >> 1];
    const bf16* sa_h = g_xhi + arow * D_DIM;
    const bf16* sa_l = g_xlo + arow * D_DIM;
    const long long brow = (long long)s * GUP + n0 + (tid >> 1);
    const bf16* sb_h = g_wgu_hi + brow * D_DIM;
    const bf16* sb_l = g_wgu_lo + brow * D_DIM;

    float acc[4][4][4];
#pragma unroll
    for (int i = 0; i < 4; i++)
#pragma unroll
        for (int j = 0; j < 4; j++)
#pragma unroll
            for (int k = 0; k < 4; k++) acc[i][j][k] = 0.f;

    gemm_mainloop(s0, sa_h, sa_l, sb_h, sb_l, D_DIM / BK, tid, acc);

    const int lane = tid & 31, wid = tid >> 5;
    const int mwb = (wid >> 2) * 64, nwb = (wid & 3) * 32;
    bf16* oh = g_act_hi + (size_t)s * T_TOKENS * IP;
    bf16* ol = g_act_lo + (size_t)s * T_TOKENS * IP;
#pragma unroll
    for (int mi = 0; mi < 4; mi++) {
        const int r0 = m0 + mwb + mi * 16 + (lane >> 2);
#pragma unroll
        for (int ni = 0; ni < 4; ni++) {
            const int acol = ((n0 + nwb + ni * 8) >> 1) + (lane & 3);
            const float* a = acc[mi][ni];
            if (r0 < M) {
                float g = a[0], u = a[1];
                float v = (g / (1.f + __expf(-g))) * u;
                bf16 h, l; split2(v, h, l);
                oh[(size_t)r0 * IP + acol] = h;
                ol[(size_t)r0 * IP + acol] = l;
            }
            if (r0 + 8 < M) {
                float g = a[2], u = a[3];
                float v = (g / (1.f + __expf(-g))) * u;
                bf16 h, l; split2(v, h, l);
                oh[(size_t)(r0 + 8) * IP + acol] = h;
                ol[(size_t)(r0 + 8) * IP + acol] = l;
            }
        }
    }
}

// ---------------- GEMM2: C = act @ down^T (slot0 -> out, 1..8 -> ybuf) ----------
__global__ void __launch_bounds__(256, 1) gemm2_kernel(float* __restrict__ out) {
    extern __shared__ char smem[];
    const uint32_t s0 = smem_u32(smem) + 1024;
    const int tid = threadIdx.x;
    const int s = blockIdx.z, m0 = blockIdx.y * BM, n0 = blockIdx.x * BN;
    const int M = (s == 0) ? T_TOKENS : g_cnt[s - 1];
    if (m0 >= M) return;

    const bf16* sa_h = g_act_hi + (size_t)s * T_TOKENS * IP + (size_t)(m0 + (tid >> 1)) * IP;
    const bf16* sa_l = g_act_lo + (size_t)s * T_TOKENS * IP + (size_t)(m0 + (tid >> 1)) * IP;
    const long long brow = (long long)s * D_DIM + n0 + (tid >> 1);
    const bf16* sb_h = g_wdn_hi + brow * IP;
    const bf16* sb_l = g_wdn_lo + brow * IP;

    float acc[4][4][4];
#pragma unroll
    for (int i = 0; i < 4; i++)
#pragma unroll
        for (int j = 0; j < 4; j++)
#pragma unroll
            for (int k = 0; k < 4; k++) acc[i][j][k] = 0.f;

    gemm_mainloop(s0, sa_h, sa_l, sb_h, sb_l, IP / BK, tid, acc);

    float* C = (s == 0) ? out : (g_ybuf + (size_t)(s - 1) * T_TOKENS * D_DIM);
    const int lane = tid & 31, wid = tid >> 5;
    const int mwb = (wid >> 2) * 64, nwb = (wid & 3) * 32;
#pragma unroll
    for (int mi = 0; mi < 4; mi++) {
        const int r0 = m0 + mwb + mi * 16 + (lane >> 2);
#pragma unroll
        for (int ni = 0; ni < 4; ni++) {
            const int n = n0 + nwb + ni * 8 + (lane & 3) * 2;
            const float* a = acc[mi][ni];
            if (r0 < M)     *(float2*)(C + (size_t)r0 * D_DIM + n)       = make_float2(a[0], a[1]);
            if (r0 + 8 < M) *(float2*)(C + (size_t)(r0 + 8) * D_DIM + n) = make_float2(a[2], a[3]);
        }
    }
}

// ---------------- combine: out[t] += w1*y[e1][p1] + w2*y[e2][p2] ----------------
__global__ void combine_kernel(float* __restrict__ out) {
    const int t = blockIdx.x;
    const int c = threadIdx.x;               // 256 threads x float4 = 1024
    const int4 e = g_tk2[t];
    const float2 w = g_w2[t];
    const float4* y1 = (const float4*)(g_ybuf + ((size_t)e.x * T_TOKENS + e.y) * D_DIM);
    const float4* y2 = (const float4*)(g_ybuf + ((size_t)e.z * T_TOKENS + e.w) * D_DIM);
    float4* o = (float4*)(out + (size_t)t * D_DIM);
    float4 a = o[c], b1 = y1[c], b2 = y2[c];
    a.x += w.x * b1.x + w.y * b2.x;
    a.y += w.x * b1.y + w.y * b2.y;
    a.z += w.x * b1.z + w.y * b2.z;
    a.w += w.x * b1.w + w.y * b2.w;
    o[c] = a;
}

// ---------------- small kernels ----------------
__global__ void zero_cnt_kernel(int* cnt) {
    if (threadIdx.x < E_EXP) cnt[threadIdx.x] = 0;
}

__global__ void split_x_kernel(const float* __restrict__ x, bf16* __restrict__ xh,
                               bf16* __restrict__ xl) {
    int i = blockIdx.x * 256 + threadIdx.x;
    float v = x[i];
    bf16 h, l; split2(v, h, l);
    xh[i] = h; xl[i] = l;
}

__global__ void repack_wgu_kernel(const float* __restrict__ sgu, const float* __restrict__ egu,
                                  bf16* __restrict__ wh, bf16* __restrict__ wl) {
    long long idx = (long long)blockIdx.x * 256 + threadIdx.x;   // 9*1920*1024 exact
    int k = (int)(idx & (D_DIM - 1));
    int r = (int)((idx >> 10) % GUP);
    int s = (int)(idx / ((long long)GUP * D_DIM));
    float v = 0.f;
    if (r < GU_DIM) {
        int sr = (r & 1) ? (r >> 1) + I_DIM : (r >> 1);
        v = (s == 0) ? sgu[(long long)sr * D_DIM + k]
                     : egu[((long long)(s - 1) * GU_DIM + sr) * D_DIM + k];
    }
    bf16 h, l; split2(v, h, l);
    wh[idx] = h; wl[idx] = l;
}

__global__ void repack_wdn_kernel(const float* __restrict__ sdn, const float* __restrict__ edn,
                                  bf16* __restrict__ wh, bf16* __restrict__ wl) {
    long long idx = (long long)blockIdx.x * 256 + threadIdx.x;   // 9*1024*960 exact
    int i = (int)(idx % IP);
    int n = (int)((idx / IP) & (D_DIM - 1));
    int s = (int)(idx / ((long long)D_DIM * IP));
    float v = 0.f;
    if (i < I_DIM) {
        v = (s == 0) ? sdn[(long long)n * I_DIM + i]
                     : edn[((long long)(s - 1) * D_DIM + n) * I_DIM + i];
    }
    bf16 h, l; split2(v, h, l);
    wh[idx] = h; wl[idx] = l;
}

// ---------------- router ----------------
__global__ void router_kernel(const float* __restrict__ x, const float* __restrict__ gw,
                              int* __restrict__ cnt, int* __restrict__ tok,
                              int4* __restrict__ tk2, float2* __restrict__ w2) {
    __shared__ float sgw[E_EXP * D_DIM];
    const int tid = threadIdx.x;
    for (int i = tid; i < E_EXP * D_DIM; i += blockDim.x) sgw[i] = gw[i];
    __syncthreads();
    const int warp = tid >> 5, lane = tid & 31;
    const int t = blockIdx.x * 8 + warp;
    const float* xt = x + (long long)t * D_DIM;
    float acc[E_EXP];
#pragma unroll
    for (int e = 0; e < E_EXP; e++) acc[e] = 0.f;
    for (int k = lane; k < D_DIM; k += 32) {
        float xv = xt[k];
#pragma unroll
        for (int e = 0; e < E_EXP; e++) acc[e] += xv * sgw[e * D_DIM + k];
    }
#pragma unroll
    for (int e = 0; e < E_EXP; e++)
#pragma unroll
        for (int off = 16; off; off >>= 1)
            acc[e] += __shfl_xor_sync(0xffffffffu, acc[e], off);
    if (lane == 0) {
        float mx = acc[0];
#pragma unroll
        for (int e = 1; e < E_EXP; e++) mx = fmaxf(mx, acc[e]);
        float p[E_EXP], Z = 0.f;
#pragma unroll
        for (int e = 0; e < E_EXP; e++) { p[e] = expf(acc[e] - mx); Z += p[e]; }
#pragma unroll
        for (int e = 0; e < E_EXP; e++) p[e] /= Z;
        int i1 = 0;
#pragma unroll
        for (int e = 1; e < E_EXP; e++) if (p[e] > p[i1]) i1 = e;
        int i2 = (i1 == 0) ? 1 : 0;
#pragma unroll
        for (int e = 0; e < E_EXP; e++) if (e != i1 && e != i2 && p[e] > p[i2]) i2 = e;
        float denom = p[i1] + p[i2] + 1e-8f;
        int pos1 = atomicAdd(&cnt[i1], 1);
        tok[i1 * T_TOKENS + pos1] = t;
        int pos2 = atomicAdd(&cnt[i2], 1);
        tok[i2 * T_TOKENS + pos2] = t;
        tk2[t] = make_int4(i1, pos1, i2, pos2);
        w2[t]  = make_float2(p[i1] / denom, p[i2] / denom);
    }
}

// ---------------- host launch ----------------
extern "C" void kernel_launch(void* const* d_in, const int* in_sizes, int n_in,
                              void* d_out, int out_size) {
    const float* x   = (const float*)d_in[0];
    const float* gw  = (const float*)d_in[1];
    const float* sgu = (const float*)d_in[2];
    const float* sdn = (const float*)d_in[3];
    const float* egu = (const float*)d_in[4];
    const float* edn = (const float*)d_in[5];
    float* out = (float*)d_out;

    cudaFuncSetAttribute(gemm1_kernel, cudaFuncAttributeMaxDynamicSharedMemorySize, SMEM_DYN);
    cudaFuncSetAttribute(gemm2_kernel, cudaFuncAttributeMaxDynamicSharedMemorySize, SMEM_DYN);

    void *pCnt, *pTok, *pTk2, *pW2, *pXh, *pXl, *pWguH, *pWguL, *pWdnH, *pWdnL;
    cudaGetSymbolAddress(&pCnt, g_cnt);
    cudaGetSymbolAddress(&pTok, g_tok);
    cudaGetSymbolAddress(&pTk2, g_tk2);
    cudaGetSymbolAddress(&pW2,  g_w2);
    cudaGetSymbolAddress(&pXh,  g_xhi);
    cudaGetSymbolAddress(&pXl,  g_xlo);
    cudaGetSymbolAddress(&pWguH, g_wgu_hi);
    cudaGetSymbolAddress(&pWguL, g_wgu_lo);
    cudaGetSymbolAddress(&pWdnH, g_wdn_hi);
    cudaGetSymbolAddress(&pWdnL, g_wdn_lo);

    // 1) router
    zero_cnt_kernel<<<1, 32>>>((int*)pCnt);
    router_kernel<<<T_TOKENS / 8, 256>>>(x, gw, (int*)pCnt, (int*)pTok,
                                         (int4*)pTk2, (float2*)pW2);

    // 2) splits / repacks
    split_x_kernel<<<(T_TOKENS * D_DIM) / 256, 256>>>(x, (bf16*)pXh, (bf16*)pXl);
    repack_wgu_kernel<<<(NSLOT * GUP * D_DIM) / 256, 256>>>(sgu, egu, (bf16*)pWguH, (bf16*)pWguL);
    repack_wdn_kernel<<<(NSLOT * D_DIM * IP) / 256, 256>>>(sdn, edn, (bf16*)pWdnH, (bf16*)pWdnL);

    // 3) GEMM1 + fused swiglu (shared + routed in one launch)
    gemm1_kernel<<<dim3(GUP / BN, T_TOKENS / BM, NSLOT), 256, SMEM_DYN>>>();

    // 4) GEMM2: slot 0 writes out, slots 1..8 write ybuf
    gemm2_kernel<<<dim3(D_DIM / BN, T_TOKENS / BM, NSLOT), 256, SMEM_DYN>>>(out);

    // 5) combine routed contributions (atomic-free)
    combine_kernel<<<T_TOKENS, 256>>>(out);
}

// round 4
// speedup vs baseline: 2.1316x; 1.0454x over previous
#include <cuda_runtime.h>
#include <cuda_bf16.h>
#include <math.h>
#include <stdint.h>

typedef __nv_bfloat16 bf16;

#define T_TOKENS 8192
#define D_DIM    1024
#define E_EXP    8
#define I_DIM    938
#define GU_DIM   1876
#define GUP      1920      // 2I padded (15*128)
#define IP       960       // I padded (15*64)
#define NSLOT    9         // slot0 = shared, 1..8 = routed

#define BM 256
#define BN 128
#define BK 64
#define SROW 144                        // 64 bf16 data + 8 bf16 pad
#define OFF_AH 0
#define OFF_AL (BM*SROW)                // 36864
#define OFF_BH (2*BM*SROW)              // 73728
#define OFF_BL (2*BM*SROW + BN*SROW)    // 92160
#define STAGEB (2*BM*SROW + 2*BN*SROW)  // 110592
#define SMEM_DYN (1024 + 2*STAGEB)      // 222208

// ---------------- static scratch ----------------
__device__ int    g_cnt[E_EXP];
__device__ int    g_tok[E_EXP * T_TOKENS];
__device__ int4   g_tk2[T_TOKENS];
__device__ float2 g_w2 [T_TOKENS];
__device__ bf16   g_xhi[T_TOKENS * D_DIM];
__device__ bf16   g_xlo[T_TOKENS * D_DIM];
__device__ bf16   g_wgu_hi[NSLOT * GUP * D_DIM];   // interleaved (gate_i, up_i) rows
__device__ bf16   g_wgu_lo[NSLOT * GUP * D_DIM];
__device__ bf16   g_wdn_hi[NSLOT * D_DIM * IP];
__device__ bf16   g_wdn_lo[NSLOT * D_DIM * IP];
__device__ bf16   g_act_hi[(size_t)NSLOT * T_TOKENS * IP];
__device__ bf16   g_act_lo[(size_t)NSLOT * T_TOKENS * IP];
__device__ float  g_ybuf[(size_t)E_EXP * T_TOKENS * D_DIM];

// ---------------- helpers ----------------
__device__ __forceinline__ uint32_t smem_u32(const void* p) {
    uint32_t a;
    asm("{ .reg .u64 t; cvta.to.shared.u64 t, %1; cvt.u32.u64 %0, t; }" : "=r"(a) : "l"(p));
    return a;
}
__device__ __forceinline__ void cp16(uint32_t s, const void* g) {
    asm volatile("cp.async.cg.shared.global [%0], [%1], 16;" :: "r"(s), "l"(g));
}
__device__ __forceinline__ void ldsm4(uint32_t* r, uint32_t a) {
    asm volatile("ldmatrix.sync.aligned.m8n8.x4.shared.b16 {%0,%1,%2,%3}, [%4];"
        : "=r"(r[0]), "=r"(r[1]), "=r"(r[2]), "=r"(r[3]) : "r"(a));
}
__device__ __forceinline__ void mma16816(float* d, const uint32_t* a, const uint32_t* b) {
    asm volatile(
        "mma.sync.aligned.m16n8k16.row.col.f32.bf16.bf16.f32 "
        "{%0,%1,%2,%3}, {%4,%5,%6,%7}, {%8,%9}, {%0,%1,%2,%3};"
        : "+f"(d[0]), "+f"(d[1]), "+f"(d[2]), "+f"(d[3])
        : "r"(a[0]), "r"(a[1]), "r"(a[2]), "r"(a[3]), "r"(b[0]), "r"(b[1]));
}
__device__ __forceinline__ void split2(float v, bf16& h, bf16& l) {
    h = __float2bfloat16(v);
    l = __float2bfloat16(v - __bfloat162float(h));
}

// ---------------- mainloop: 256x128 CTA tile, 64x64 warp tile, 3-term split ----------
__device__ __forceinline__ void gemm_mainloop(
    uint32_t s0,
    const bf16* sa_h, const bf16* sa_l,   // per-thread A row ptr (row = tid)
    const bf16* sb_h, const bf16* sb_l,   // per-thread B row ptr (row = tid>>1)
    int NC, int tid, float acc[4][8][4])
{
    const int lane = tid & 31, wid = tid >> 5;
    const uint32_t aoff = (uint32_t)tid * SROW;
    const uint32_t boff = (uint32_t)(tid >> 1) * SROW + (uint32_t)(tid & 1) * 64;
    const int bkel = (tid & 1) * 32;

#define LOAD_STAGE(st, c) do {                                              \
        uint32_t base_ = s0 + (st) * STAGEB;                                \
        int k0_ = (c) * BK;                                                 \
        _Pragma("unroll")                                                   \
        for (int j = 0; j < 8; j++) {                                       \
            cp16(base_ + OFF_AH + aoff + j*16, sa_h + k0_ + j*8);           \
            cp16(base_ + OFF_AL + aoff + j*16, sa_l + k0_ + j*8);           \
        }                                                                   \
        _Pragma("unroll")                                                   \
        for (int j = 0; j < 4; j++) {                                       \
            cp16(base_ + OFF_BH + boff + j*16, sb_h + k0_ + bkel + j*8);    \
            cp16(base_ + OFF_BL + boff + j*16, sb_l + k0_ + bkel + j*8);    \
        }                                                                   \
        asm volatile("cp.async.commit_group;" ::: "memory");                \
    } while (0)

    LOAD_STAGE(0, 0);

    const int mwb = (wid >> 1) * 64;
    const int nwb = (wid & 1) * 64;
    const int arow   = mwb + (lane & 15);
    const int acolB0 = (lane >> 4) * 16;
    const int bnrow  = nwb + ((lane >> 4) * 8) + (lane & 7);
    const int bkB0   = ((lane >> 3) & 1) * 16;

    for (int c = 0; c < NC; c++) {
        const int st = c & 1;
        if (c + 1 < NC) {
            LOAD_STAGE(st ^ 1, c + 1);
            asm volatile("cp.async.wait_group 1;" ::: "memory");
        } else {
            asm volatile("cp.async.wait_group 0;" ::: "memory");
        }
        __syncthreads();
        const uint32_t tb = s0 + st * STAGEB;
#pragma unroll
        for (int ks = 0; ks < 4; ks++) {
            uint32_t ah[4][4], al[4][4];
            const uint32_t acolB = ks * 32 + acolB0;
#pragma unroll
            for (int mi = 0; mi < 4; mi++) {
                uint32_t ra = tb + (uint32_t)(arow + mi * 16) * SROW + acolB;
                ldsm4(ah[mi], ra + OFF_AH);
                ldsm4(al[mi], ra + OFF_AL);
            }
            const uint32_t bcolB = ks * 32 + bkB0;
#pragma unroll
            for (int nb = 0; nb < 4; nb++) {
                uint32_t bh[4], bl[4];
                uint32_t rb = tb + (uint32_t)(bnrow + nb * 16) * SROW + bcolB;
                ldsm4(bh, rb + OFF_BH);
                ldsm4(bl, rb + OFF_BL);
#pragma unroll
                for (int mi = 0; mi < 4; mi++) {
                    mma16816(acc[mi][nb * 2 + 0], ah[mi], bh + 0);
                    mma16816(acc[mi][nb * 2 + 0], ah[mi], bl + 0);
                    mma16816(acc[mi][nb * 2 + 0], al[mi], bh + 0);
                    mma16816(acc[mi][nb * 2 + 1], ah[mi], bh + 2);
                    mma16816(acc[mi][nb * 2 + 1], ah[mi], bl + 2);
                    mma16816(acc[mi][nb * 2 + 1], al[mi], bh + 2);
                }
            }
        }
        __syncthreads();
    }
#undef LOAD_STAGE
}

// ---------------- GEMM1: H = X @ Wgu^T, fused swiglu -> act hi/lo ----------------
__global__ void __launch_bounds__(256, 1) gemm1_kernel() {
    extern __shared__ char smem[];
    int* rowids = (int*)smem;
    const uint32_t s0 = smem_u32(smem) + 1024;
    const int tid = threadIdx.x;
    const int s = blockIdx.z, m0 = blockIdx.y * BM, n0 = blockIdx.x * BN;
    const int M = (s == 0) ? T_TOKENS : g_cnt[s - 1];
    if (m0 >= M) return;

    {
        int am = m0 + tid;
        int r;
        if (s == 0) r = (am < M ? am : M - 1);
        else        r = g_tok[(s - 1) * T_TOKENS + (am < M ? am : M - 1)];
        rowids[tid] = r;
    }
    __syncthreads();

    const long long arow = rowids[tid];
    const bf16* sa_h = g_xhi + arow * D_DIM;
    const bf16* sa_l = g_xlo + arow * D_DIM;
    const long long brow = (long long)s * GUP + n0 + (tid >> 1);
    const bf16* sb_h = g_wgu_hi + brow * D_DIM;
    const bf16* sb_l = g_wgu_lo + brow * D_DIM;

    float acc[4][8][4];
#pragma unroll
    for (int i = 0; i < 4; i++)
#pragma unroll
        for (int j = 0; j < 8; j++)
#pragma unroll
            for (int k = 0; k < 4; k++) acc[i][j][k] = 0.f;

    gemm_mainloop(s0, sa_h, sa_l, sb_h, sb_l, D_DIM / BK, tid, acc);

    const int lane = tid & 31, wid = tid >> 5;
    const int mwb = (wid >> 1) * 64, nwb = (wid & 1) * 64;
    bf16* oh = g_act_hi + (size_t)s * T_TOKENS * IP;
    bf16* ol = g_act_lo + (size_t)s * T_TOKENS * IP;
#pragma unroll
    for (int mi = 0; mi < 4; mi++) {
        const int r0 = m0 + mwb + mi * 16 + (lane >> 2);
#pragma unroll
        for (int j = 0; j < 8; j++) {
            const int nbase = n0 + nwb + (j >> 1) * 16 + (j & 1) * 8 + (lane & 3) * 2;
            const int acol = nbase >> 1;
            const float* a = acc[mi][j];
            if (r0 < M) {
                float g = a[0], u = a[1];
                float v = (g / (1.f + __expf(-g))) * u;
                bf16 h, l; split2(v, h, l);
                oh[(size_t)r0 * IP + acol] = h;
                ol[(size_t)r0 * IP + acol] = l;
            }
            if (r0 + 8 < M) {
                float g = a[2], u = a[3];
                float v = (g / (1.f + __expf(-g))) * u;
                bf16 h, l; split2(v, h, l);
                oh[(size_t)(r0 + 8) * IP + acol] = h;
                ol[(size_t)(r0 + 8) * IP + acol] = l;
            }
        }
    }
}

// ---------------- GEMM2: C = act @ down^T (slot0 -> out, 1..8 -> ybuf) ----------
__global__ void __launch_bounds__(256, 1) gemm2_kernel(float* __restrict__ out) {
    extern __shared__ char smem[];
    const uint32_t s0 = smem_u32(smem) + 1024;
    const int tid = threadIdx.x;
    const int s = blockIdx.z, m0 = blockIdx.y * BM, n0 = blockIdx.x * BN;
    const int M = (s == 0) ? T_TOKENS : g_cnt[s - 1];
    if (m0 >= M) return;

    const int amr = m0 + tid < T_TOKENS ? m0 + tid : T_TOKENS - 1;
    const bf16* sa_h = g_act_hi + (size_t)s * T_TOKENS * IP + (size_t)amr * IP;
    const bf16* sa_l = g_act_lo + (size_t)s * T_TOKENS * IP + (size_t)amr * IP;
    const long long brow = (long long)s * D_DIM + n0 + (tid >> 1);
    const bf16* sb_h = g_wdn_hi + brow * IP;
    const bf16* sb_l = g_wdn_lo + brow * IP;

    float acc[4][8][4];
#pragma unroll
    for (int i = 0; i < 4; i++)
#pragma unroll
        for (int j = 0; j < 8; j++)
#pragma unroll
            for (int k = 0; k < 4; k++) acc[i][j][k] = 0.f;

    gemm_mainloop(s0, sa_h, sa_l, sb_h, sb_l, IP / BK, tid, acc);

    float* C = (s == 0) ? out : (g_ybuf + (size_t)(s - 1) * T_TOKENS * D_DIM);
    const int lane = tid & 31, wid = tid >> 5;
    const int mwb = (wid >> 1) * 64, nwb = (wid & 1) * 64;
#pragma unroll
    for (int mi = 0; mi < 4; mi++) {
        const int r0 = m0 + mwb + mi * 16 + (lane >> 2);
#pragma unroll
        for (int j = 0; j < 8; j++) {
            const int n = n0 + nwb + (j >> 1) * 16 + (j & 1) * 8 + (lane & 3) * 2;
            const float* a = acc[mi][j];
            if (r0 < M)     *(float2*)(C + (size_t)r0 * D_DIM + n)       = make_float2(a[0], a[1]);
            if (r0 + 8 < M) *(float2*)(C + (size_t)(r0 + 8) * D_DIM + n) = make_float2(a[2], a[3]);
        }
    }
}

// ---------------- combine: out[t] += w1*y[e1][p1] + w2*y[e2][p2] ----------------
__global__ void combine_kernel(float* __restrict__ out) {
    const int t = blockIdx.x;
    const int c = threadIdx.x;
    const int4 e = g_tk2[t];
    const float2 w = g_w2[t];
    const float4* y1 = (const float4*)(g_ybuf + ((size_t)e.x * T_TOKENS + e.y) * D_DIM);
    const float4* y2 = (const float4*)(g_ybuf + ((size_t)e.z * T_TOKENS + e.w) * D_DIM);
    float4* o = (float4*)(out + (size_t)t * D_DIM);
    float4 a = o[c], b1 = y1[c], b2 = y2[c];
    a.x += w.x * b1.x + w.y * b2.x;
    a.y += w.x * b1.y + w.y * b2.y;
    a.z += w.x * b1.z + w.y * b2.z;
    a.w += w.x * b1.w + w.y * b2.w;
    o[c] = a;
}

// ---------------- prep kernels (div/mod-free, vectorized) ----------------
__global__ void zero_cnt_kernel(int* cnt) {
    if (threadIdx.x < E_EXP) cnt[threadIdx.x] = 0;
}

__global__ void split_x_kernel(const float* __restrict__ x, bf16* __restrict__ xh,
                               bf16* __restrict__ xl) {
    const int i4 = (blockIdx.x * 256 + threadIdx.x) * 4;
    float4 v = *(const float4*)(x + i4);
    __align__(8) bf16 h[4], l[4];
    split2(v.x, h[0], l[0]); split2(v.y, h[1], l[1]);
    split2(v.z, h[2], l[2]); split2(v.w, h[3], l[3]);
    *(uint2*)(xh + i4) = *(const uint2*)h;
    *(uint2*)(xl + i4) = *(const uint2*)l;
}

// grid (GUP, NSLOT), block 256: thread covers 4 k (1024 = 256*4)
__global__ void repack_wgu_kernel(const float* __restrict__ sgu, const float* __restrict__ egu,
                                  bf16* __restrict__ wh, bf16* __restrict__ wl) {
    const int r = blockIdx.x, s = blockIdx.y;
    const int k4 = threadIdx.x * 4;
    const size_t dst = ((size_t)s * GUP + r) * D_DIM + k4;
    float4 v = make_float4(0.f, 0.f, 0.f, 0.f);
    if (r < GU_DIM) {
        const int sr = (r & 1) ? (r >> 1) + I_DIM : (r >> 1);
        const float* src = (s == 0) ? (sgu + (size_t)sr * D_DIM)
                                    : (egu + ((size_t)(s - 1) * GU_DIM + sr) * D_DIM);
        v = *(const float4*)(src + k4);
    }
    __align__(8) bf16 h[4], l[4];
    split2(v.x, h[0], l[0]); split2(v.y, h[1], l[1]);
    split2(v.z, h[2], l[2]); split2(v.w, h[3], l[3]);
    *(uint2*)(wh + dst) = *(const uint2*)h;
    *(uint2*)(wl + dst) = *(const uint2*)l;
}

// grid (D_DIM, NSLOT), block 240: thread covers 4 i (960 = 240*4)
__global__ void repack_wdn_kernel(const float* __restrict__ sdn, const float* __restrict__ edn,
                                  bf16* __restrict__ wh, bf16* __restrict__ wl) {
    const int n = blockIdx.x, s = blockIdx.y;
    const int k4 = threadIdx.x * 4;
    const size_t dst = ((size_t)s * D_DIM + n) * IP + k4;
    const float* src = (s == 0) ? (sdn + (size_t)n * I_DIM)
                                : (edn + ((size_t)(s - 1) * D_DIM + n) * I_DIM);
    __align__(8) bf16 h[4], l[4];
#pragma unroll
    for (int q = 0; q < 4; q++) {
        const int i = k4 + q;
        float v = (i < I_DIM) ? __ldg(src + i) : 0.f;
        split2(v, h[q], l[q]);
    }
    *(uint2*)(wh + dst) = *(const uint2*)h;
    *(uint2*)(wl + dst) = *(const uint2*)l;
}

// ---------------- router ----------------
__global__ void router_kernel(const float* __restrict__ x, const float* __restrict__ gw,
                              int* __restrict__ cnt, int* __restrict__ tok,
                              int4* __restrict__ tk2, float2* __restrict__ w2) {
    __shared__ float sgw[E_EXP * D_DIM];
    const int tid = threadIdx.x;
    for (int i = tid; i < E_EXP * D_DIM; i += blockDim.x) sgw[i] = gw[i];
    __syncthreads();
    const int warp = tid >> 5, lane = tid & 31;
    const int t = blockIdx.x * 8 + warp;
    const float* xt = x + (long long)t * D_DIM;
    float acc[E_EXP];
#pragma unroll
    for (int e = 0; e < E_EXP; e++) acc[e] = 0.f;
    for (int k = lane; k < D_DIM; k += 32) {
        float xv = xt[k];
#pragma unroll
        for (int e = 0; e < E_EXP; e++) acc[e] += xv * sgw[e * D_DIM + k];
    }
#pragma unroll
    for (int e = 0; e < E_EXP; e++)
#pragma unroll
        for (int off = 16; off; off >>= 1)
            acc[e] += __shfl_xor_sync(0xffffffffu, acc[e], off);
    if (lane == 0) {
        float mx = acc[0];
#pragma unroll
        for (int e = 1; e < E_EXP; e++) mx = fmaxf(mx, acc[e]);
        float p[E_EXP], Z = 0.f;
#pragma unroll
        for (int e = 0; e < E_EXP; e++) { p[e] = expf(acc[e] - mx); Z += p[e]; }
#pragma unroll
        for (int e = 0; e < E_EXP; e++) p[e] /= Z;
        int i1 = 0;
#pragma unroll
        for (int e = 1; e < E_EXP; e++) if (p[e] > p[i1]) i1 = e;
        int i2 = (i1 == 0) ? 1 : 0;
#pragma unroll
        for (int e = 0; e < E_EXP; e++) if (e != i1 && e != i2 && p[e] > p[i2]) i2 = e;
        float denom = p[i1] + p[i2] + 1e-8f;
        int pos1 = atomicAdd(&cnt[i1], 1);
        tok[i1 * T_TOKENS + pos1] = t;
        int pos2 = atomicAdd(&cnt[i2], 1);
        tok[i2 * T_TOKENS + pos2] = t;
        tk2[t] = make_int4(i1, pos1, i2, pos2);
        w2[t]  = make_float2(p[i1] / denom, p[i2] / denom);
    }
}

// ---------------- host launch ----------------
extern "C" void kernel_launch(void* const* d_in, const int* in_sizes, int n_in,
                              void* d_out, int out_size) {
    const float* x   = (const float*)d_in[0];
    const float* gw  = (const float*)d_in[1];
    const float* sgu = (const float*)d_in[2];
    const float* sdn = (const float*)d_in[3];
    const float* egu = (const float*)d_in[4];
    const float* edn = (const float*)d_in[5];
    float* out = (float*)d_out;

    cudaFuncSetAttribute(gemm1_kernel, cudaFuncAttributeMaxDynamicSharedMemorySize, SMEM_DYN);
    cudaFuncSetAttribute(gemm2_kernel, cudaFuncAttributeMaxDynamicSharedMemorySize, SMEM_DYN);

    void *pCnt, *pTok, *pTk2, *pW2, *pXh, *pXl, *pWguH, *pWguL, *pWdnH, *pWdnL;
    cudaGetSymbolAddress(&pCnt, g_cnt);
    cudaGetSymbolAddress(&pTok, g_tok);
    cudaGetSymbolAddress(&pTk2, g_tk2);
    cudaGetSymbolAddress(&pW2,  g_w2);
    cudaGetSymbolAddress(&pXh,  g_xhi);
    cudaGetSymbolAddress(&pXl,  g_xlo);
    cudaGetSymbolAddress(&pWguH, g_wgu_hi);
    cudaGetSymbolAddress(&pWguL, g_wgu_lo);
    cudaGetSymbolAddress(&pWdnH, g_wdn_hi);
    cudaGetSymbolAddress(&pWdnL, g_wdn_lo);

    // 1) router
    zero_cnt_kernel<<<1, 32>>>((int*)pCnt);
    router_kernel<<<T_TOKENS / 8, 256>>>(x, gw, (int*)pCnt, (int*)pTok,
                                         (int4*)pTk2, (float2*)pW2);

    // 2) splits / repacks
    split_x_kernel<<<(T_TOKENS * D_DIM) / 1024, 256>>>(x, (bf16*)pXh, (bf16*)pXl);
    repack_wgu_kernel<<<dim3(GUP, NSLOT), 256>>>(sgu, egu, (bf16*)pWguH, (bf16*)pWguL);
    repack_wdn_kernel<<<dim3(D_DIM, NSLOT), 240>>>(sdn, edn, (bf16*)pWdnH, (bf16*)pWdnL);

    // 3) GEMM1 + fused swiglu (shared + routed)
    gemm1_kernel<<<dim3(GUP / BN, T_TOKENS / BM, NSLOT), 256, SMEM_DYN>>>();

    // 4) GEMM2: slot 0 writes out, slots 1..8 write ybuf
    gemm2_kernel<<<dim3(D_DIM / BN, T_TOKENS / BM, NSLOT), 256, SMEM_DYN>>>(out);

    // 5) combine routed contributions (atomic-free)
    combine_kernel<<<T_TOKENS, 256>>>(out);
}